// round 4
// baseline (speedup 1.0000x reference)
#include <cuda_runtime.h>

// Problem constants (fixed by the dataset)
#define N0   500000
#define RG   100000
#define NDST 50000
#define E0C  2000000
#define E1C  1000000
// dims: NODE_DIM=REVIEW_DIM=64, H=4, FINAL_DIM=32, H*FD=128

// -------- scratch (device globals; no runtime allocation) --------
__device__ float  g_rsum[RG * 64];     // per-review-graph sum, later r (in-place)
__device__ float  g_feat[RG * 128];    // feat_src = r @ Wsrc + bsrc
__device__ float4 g_pex [RG];          // exp(score) per REVIEW NODE, 4 heads
__device__ float  g_ssum[NDST * 4];    // softmax denominators
__device__ int    g_cnt [RG];          // nodes per review graph

// sm_90+ vectorized global reduction: one LTS op for 4 floats
__device__ __forceinline__ void red_add_v4(float* p, float4 v) {
    asm volatile("red.global.add.v4.f32 [%0], {%1,%2,%3,%4};"
                 :: "l"(p), "f"(v.x), "f"(v.y), "f"(v.z), "f"(v.w)
                 : "memory");
}

__device__ __forceinline__ float leakyf(float v, float s) {
    return v >= 0.f ? v : s * v;
}

// -------- K0: zero all accumulators + output --------
__global__ void k_init(float* __restrict__ out) {
    int i = blockIdx.x * blockDim.x + threadIdx.x;
    int stride = gridDim.x * blockDim.x;
    for (int j = i; j < RG * 64;   j += stride) g_rsum[j] = 0.f;
    for (int j = i; j < NDST * 4;  j += stride) g_ssum[j] = 0.f;
    for (int j = i; j < RG;        j += stride) g_cnt[j]  = 0;
    for (int j = i; j < NDST * 32; j += stride) out[j]    = 0.f;
}

// -------- K1: node counts per review graph --------
__global__ void k_cnt(const int* __restrict__ node_graph) {
    int i = blockIdx.x * blockDim.x + threadIdx.x;
    if (i < N0) atomicAdd(&g_cnt[node_graph[i]], 1);
}

// -------- K2: fused hyperedge scatter (skips h[N0,64] entirely) --------
// r_sum[node_graph[dst0[e]]] += x[src0[e]] * coef(e)
// 16 lanes per edge, one float4 per lane (256B coalesced gather per edge).
__global__ void k_scatter0(const float4* __restrict__ x4,
                           const float*  __restrict__ norm_n,
                           const float*  __restrict__ norm_e,
                           const int*    __restrict__ src0,
                           const int*    __restrict__ dst0,
                           const int*    __restrict__ node_graph) {
    long long t = (long long)blockIdx.x * blockDim.x + threadIdx.x;
    int e    = (int)(t >> 4);
    int lane = (int)(t & 15);
    if (e >= E0C) return;
    int s = __ldg(&src0[e]);
    int d = __ldg(&dst0[e]);
    float coef = __ldg(&norm_n[s]) * __ldg(&norm_n[d]) * __ldg(&norm_e[e]);
    int g = __ldg(&node_graph[d]);
    float4 v = __ldg(&x4[(long long)s * 16 + lane]);
    v.x *= coef; v.y *= coef; v.z *= coef; v.w *= coef;
    red_add_v4(&g_rsum[(long long)g * 64 + lane * 4], v);
}

// -------- K3: r = leaky((rsum/cnt) @ W1 + b1, 0.01), in-place into g_rsum --------
// 256 threads = 16 rows x 16 col-quads; 64 rows per block; W1 float4 in shared.
__global__ void k_mlp1(const float4* __restrict__ W1f4, const float* __restrict__ b1) {
    __shared__ float4 sW[64 * 16];     // 16KB : W1[k][c4]
    __shared__ float  srow[16][68];    // padded: no bank conflict on broadcast
    int tid = threadIdx.x;
    for (int i = tid; i < 64 * 16; i += 256) sW[i] = W1f4[i];
    int c4 = tid & 15;
    int rl = tid >> 4;                 // 0..15
    float4 bias = __ldg(&((const float4*)b1)[c4]);
    for (int t = 0; t < 4; ++t) {
        int row = blockIdx.x * 64 + t * 16 + rl;
        __syncthreads();
        if (row < RG) {
            float4 v = ((const float4*)g_rsum)[(long long)row * 16 + c4];
            *(float4*)&srow[rl][c4 * 4] = v;
        }
        __syncthreads();
        if (row < RG) {
            float4 acc = make_float4(0.f, 0.f, 0.f, 0.f);
            #pragma unroll
            for (int k = 0; k < 64; ++k) {
                float b = srow[rl][k];
                float4 w = sW[k * 16 + c4];
                acc.x += b * w.x; acc.y += b * w.y;
                acc.z += b * w.z; acc.w += b * w.w;
            }
            float cinv = 1.0f / (float)g_cnt[row];
            acc.x = leakyf(acc.x * cinv + bias.x, 0.01f);
            acc.y = leakyf(acc.y * cinv + bias.y, 0.01f);
            acc.z = leakyf(acc.z * cinv + bias.z, 0.01f);
            acc.w = leakyf(acc.w * cinv + bias.w, 0.01f);
            ((float4*)g_rsum)[(long long)row * 16 + c4] = acc;
        }
    }
}

// -------- K4: feat = r @ Wsrc + bsrc  ([RG,128]) --------
// 256 threads = 8 rows x 32 col-quads; 64 rows per block; Wsrc float4 in shared.
__global__ void k_mlp2(const float4* __restrict__ Wsf4, const float* __restrict__ bsrc) {
    __shared__ float4 sW[64 * 32];     // 32KB : Wsrc[k][c4]
    __shared__ float  srow[8][68];
    int tid = threadIdx.x;
    for (int i = tid; i < 64 * 32; i += 256) sW[i] = Wsf4[i];
    int c4 = tid & 31;
    int rl = tid >> 5;                 // 0..7
    float4 bias = __ldg(&((const float4*)bsrc)[c4]);
    for (int t = 0; t < 8; ++t) {
        int row = blockIdx.x * 64 + t * 8 + rl;
        __syncthreads();
        if (row < RG && c4 < 16) {
            float4 v = ((const float4*)g_rsum)[(long long)row * 16 + c4];
            *(float4*)&srow[rl][c4 * 4] = v;
        }
        __syncthreads();
        if (row < RG) {
            float4 acc = make_float4(bias.x, bias.y, bias.z, bias.w);
            #pragma unroll
            for (int k = 0; k < 64; ++k) {
                float b = srow[rl][k];
                float4 w = sW[k * 32 + c4];
                acc.x += b * w.x; acc.y += b * w.y;
                acc.z += b * w.z; acc.w += b * w.w;
            }
            ((float4*)g_feat)[(long long)row * 32 + c4] = acc;
        }
    }
}

// -------- K5: per-review-node attention score (hoisted out of the edge loop)
// pex[r][h] = exp( sum_d leaky(feat[r,h,d], 0.2) * attn[h,d] )
// Warp per row: lane l holds dims [4l,4l+4); head = l/8.
__global__ void k_prescore(const float* __restrict__ attn) {
    long long t = (long long)blockIdx.x * blockDim.x + threadIdx.x;
    int r    = (int)(t >> 5);
    int lane = (int)(t & 31);
    if (r >= RG) return;
    float4 v = ((const float4*)g_feat)[(long long)r * 32 + lane];
    float4 lv;
    lv.x = leakyf(v.x, 0.2f); lv.y = leakyf(v.y, 0.2f);
    lv.z = leakyf(v.z, 0.2f); lv.w = leakyf(v.w, 0.2f);
    float4 a = __ldg(&((const float4*)attn)[lane]);
    float p = lv.x * a.x + lv.y * a.y + lv.z * a.z + lv.w * a.w;
    p += __shfl_xor_sync(0xffffffffu, p, 4);
    p += __shfl_xor_sync(0xffffffffu, p, 2);
    p += __shfl_xor_sync(0xffffffffu, p, 1);
    float ex = __expf(p);
    float e1 = __shfl_sync(0xffffffffu, ex, 8);
    float e2 = __shfl_sync(0xffffffffu, ex, 16);
    float e3 = __shfl_sync(0xffffffffu, ex, 24);
    if (lane == 0) g_pex[r] = make_float4(ex, e1, e2, e3);
}

// -------- K6: softmax denominators (16B gather + 16B red per edge) --------
__global__ void k_score(const int* __restrict__ src1,
                        const int* __restrict__ dst1) {
    int e = blockIdx.x * blockDim.x + threadIdx.x;
    if (e >= E1C) return;
    int s = __ldg(&src1[e]);
    int d = __ldg(&dst1[e]);
    float4 ex = __ldg((const float4*)&g_pex[s]);
    red_add_v4(&g_ssum[(long long)d * 4], ex);
}

// -------- K7: weighted aggregation into output --------
// 8 lanes per edge; lane sub covers output dims [4*sub, 4*sub+4).
// out[dst,d] += sum_h alpha[h] * feat[src, h*32+d],  alpha = pex[src]/ssum[dst]
__global__ void k_aggr(const int* __restrict__ src1,
                       const int* __restrict__ dst1,
                       float* __restrict__ out) {
    long long t = (long long)blockIdx.x * blockDim.x + threadIdx.x;
    int e   = (int)(t >> 3);
    int sub = (int)(t & 7);
    if (e >= E1C) return;
    int s = __ldg(&src1[e]);
    int d = __ldg(&dst1[e]);
    float4 exv = __ldg((const float4*)&g_pex[s]);
    float4 sv  = *(const float4*)&g_ssum[(long long)d * 4];
    float a0 = __fdividef(exv.x, sv.x);
    float a1 = __fdividef(exv.y, sv.y);
    float a2 = __fdividef(exv.z, sv.z);
    float a3 = __fdividef(exv.w, sv.w);
    const float4* f4 = (const float4*)g_feat + (long long)s * 32 + sub;
    float4 v0 = __ldg(f4 + 0);
    float4 v1 = __ldg(f4 + 8);
    float4 v2 = __ldg(f4 + 16);
    float4 v3 = __ldg(f4 + 24);
    float4 acc;
    acc.x = a0 * v0.x + a1 * v1.x + a2 * v2.x + a3 * v3.x;
    acc.y = a0 * v0.y + a1 * v1.y + a2 * v2.y + a3 * v3.y;
    acc.z = a0 * v0.z + a1 * v1.z + a2 * v2.z + a3 * v3.z;
    acc.w = a0 * v0.w + a1 * v1.w + a2 * v2.w + a3 * v3.w;
    red_add_v4(&out[(long long)d * 32 + sub * 4], acc);
}

extern "C" void kernel_launch(void* const* d_in, const int* in_sizes, int n_in,
                              void* d_out, int out_size) {
    const float* x          = (const float*)d_in[0];
    const float* norm_n     = (const float*)d_in[1];
    const float* norm_e     = (const float*)d_in[2];
    const float* W1         = (const float*)d_in[3];
    const float* b1         = (const float*)d_in[4];
    const float* Wsrc       = (const float*)d_in[5];
    const float* bsrc       = (const float*)d_in[6];
    const float* attn       = (const float*)d_in[7];
    const int*   src0       = (const int*)d_in[8];
    const int*   dst0       = (const int*)d_in[9];
    const int*   node_graph = (const int*)d_in[10];
    const int*   src1       = (const int*)d_in[11];
    const int*   dst1       = (const int*)d_in[12];
    float* out = (float*)d_out;

    k_init<<<2048, 256>>>(out);
    k_cnt<<<(N0 + 255) / 256, 256>>>(node_graph);
    {
        long long threads = (long long)E0C * 16;
        k_scatter0<<<(unsigned)((threads + 255) / 256), 256>>>(
            (const float4*)x, norm_n, norm_e, src0, dst0, node_graph);
    }
    k_mlp1<<<(RG + 63) / 64, 256>>>((const float4*)W1, b1);
    k_mlp2<<<(RG + 63) / 64, 256>>>((const float4*)Wsrc, bsrc);
    {
        long long threads = (long long)RG * 32;
        k_prescore<<<(unsigned)((threads + 255) / 256), 256>>>(attn);
    }
    k_score<<<(E1C + 255) / 256, 256>>>(src1, dst1);
    {
        long long threads = (long long)E1C * 8;
        k_aggr<<<(unsigned)((threads + 255) / 256), 256>>>(src1, dst1, out);
    }
}

// round 5
// speedup vs baseline: 1.3553x; 1.3553x over previous
#include <cuda_runtime.h>

// Problem constants (fixed by the dataset)
#define N0   500000
#define RG   100000
#define NDST 50000
#define E0C  2000000
#define E1C  1000000
// dims: NODE_DIM=REVIEW_DIM=64, H=4, FINAL_DIM=32, H*FD=128

// -------- scratch (device globals; no runtime allocation) --------
__device__ float  g_rsum[RG * 64];     // per-review-graph sum, later r (in-place)
__device__ float  g_feat[RG * 128];    // feat_src = r @ Wsrc + bsrc
__device__ float4 g_pex [RG];          // exp(score) per REVIEW NODE, 4 heads
__device__ float  g_ssum[NDST * 4];    // softmax denominators
__device__ int    g_cnt [RG];          // nodes per review graph

// sm_90+ vectorized global reduction: one LTS op for 4 floats
__device__ __forceinline__ void red_add_v4(float* p, float4 v) {
    asm volatile("red.global.add.v4.f32 [%0], {%1,%2,%3,%4};"
                 :: "l"(p), "f"(v.x), "f"(v.y), "f"(v.z), "f"(v.w)
                 : "memory");
}

__device__ __forceinline__ float leakyf(float v, float s) {
    return v >= 0.f ? v : s * v;
}

// sm_100+ packed dual-fp32 FMA (2 IEEE fp32 FMAs in one instruction)
#define FMA2(acc, a, b) \
    asm("fma.rn.f32x2 %0, %1, %2, %0;" : "+l"(acc) : "l"(a), "l"(b))

__device__ __forceinline__ unsigned long long pack2(float b) {
    unsigned long long r;
    unsigned int u = __float_as_uint(b);
    asm("mov.b64 %0, {%1, %1};" : "=l"(r) : "r"(u));
    return r;
}
__device__ __forceinline__ float lo32(unsigned long long v) {
    return __uint_as_float((unsigned int)v);
}
__device__ __forceinline__ float hi32(unsigned long long v) {
    return __uint_as_float((unsigned int)(v >> 32));
}

// -------- K0: zero all accumulators + output --------
__global__ void k_init(float* __restrict__ out) {
    int i = blockIdx.x * blockDim.x + threadIdx.x;
    int stride = gridDim.x * blockDim.x;
    for (int j = i; j < RG * 64;   j += stride) g_rsum[j] = 0.f;
    for (int j = i; j < NDST * 4;  j += stride) g_ssum[j] = 0.f;
    for (int j = i; j < RG;        j += stride) g_cnt[j]  = 0;
    for (int j = i; j < NDST * 32; j += stride) out[j]    = 0.f;
}

// -------- K1: node counts per review graph --------
__global__ void k_cnt(const int* __restrict__ node_graph) {
    int i = blockIdx.x * blockDim.x + threadIdx.x;
    if (i < N0) atomicAdd(&g_cnt[node_graph[i]], 1);
}

// -------- K2: fused hyperedge scatter (skips h[N0,64] entirely) --------
__global__ void k_scatter0(const float4* __restrict__ x4,
                           const float*  __restrict__ norm_n,
                           const float*  __restrict__ norm_e,
                           const int*    __restrict__ src0,
                           const int*    __restrict__ dst0,
                           const int*    __restrict__ node_graph) {
    long long t = (long long)blockIdx.x * blockDim.x + threadIdx.x;
    int e    = (int)(t >> 4);
    int lane = (int)(t & 15);
    if (e >= E0C) return;
    int s = __ldg(&src0[e]);
    int d = __ldg(&dst0[e]);
    float coef = __ldg(&norm_n[s]) * __ldg(&norm_n[d]) * __ldg(&norm_e[e]);
    int g = __ldg(&node_graph[d]);
    float4 v = __ldg(&x4[(long long)s * 16 + lane]);
    v.x *= coef; v.y *= coef; v.z *= coef; v.w *= coef;
    red_add_v4(&g_rsum[(long long)g * 64 + lane * 4], v);
}

// -------- K3: r = leaky((rsum/cnt) @ W1 + b1, 0.01), in-place into g_rsum ----
// 64-row tile; 256 threads = 16 rl x 16 c4; each thread does 4 rows x 4 cols.
// One sW LDS.128 per k feeds 4 rows (register row-blocking); FFMA2 packed math.
__global__ void k_mlp1(const float4* __restrict__ W1f4, const float* __restrict__ b1) {
    __shared__ float4 sW[64 * 16];     // 16KB : W1[k][c4]
    __shared__ float  srow[64][68];    // padded rows
    int tid = threadIdx.x;
    for (int i = tid; i < 64 * 16; i += 256) sW[i] = W1f4[i];
    int c4 = tid & 15;
    int rl = tid >> 4;                 // 0..15
    float4 bias = __ldg(&((const float4*)b1)[c4]);
    int base = blockIdx.x * 64;
    #pragma unroll
    for (int j = 0; j < 4; ++j) {
        int row = base + rl + 16 * j;
        if (row < RG)
            *(float4*)&srow[rl + 16 * j][c4 * 4] =
                ((const float4*)g_rsum)[(long long)row * 16 + c4];
    }
    __syncthreads();
    unsigned long long a0[4] = {0,0,0,0}, a1[4] = {0,0,0,0};
    const ulonglong2* sW2 = (const ulonglong2*)sW;
    #pragma unroll 8
    for (int k = 0; k < 64; ++k) {
        ulonglong2 w = sW2[k * 16 + c4];
        #pragma unroll
        for (int j = 0; j < 4; ++j) {
            unsigned long long bb = pack2(srow[rl + 16 * j][k]);
            FMA2(a0[j], w.x, bb);
            FMA2(a1[j], w.y, bb);
        }
    }
    #pragma unroll
    for (int j = 0; j < 4; ++j) {
        int row = base + rl + 16 * j;
        if (row < RG) {
            float cinv = 1.0f / (float)g_cnt[row];
            float4 v;
            v.x = leakyf(lo32(a0[j]) * cinv + bias.x, 0.01f);
            v.y = leakyf(hi32(a0[j]) * cinv + bias.y, 0.01f);
            v.z = leakyf(lo32(a1[j]) * cinv + bias.z, 0.01f);
            v.w = leakyf(hi32(a1[j]) * cinv + bias.w, 0.01f);
            ((float4*)g_rsum)[(long long)row * 16 + c4] = v;
        }
    }
}

// -------- K4: feat = r @ Wsrc + bsrc  ([RG,128])  + FUSED attention prescore --
// 32-row tile; 256 threads = 8 rl(warps) x 32 c4(lanes); 4 rows/thread.
// Epilogue computes pex[r][h] = exp(sum_d leaky(feat)*attn) from registers.
__global__ void k_mlp2s(const float4* __restrict__ Wsf4,
                        const float*  __restrict__ bsrc,
                        const float*  __restrict__ attn) {
    __shared__ float4 sW[64 * 32];     // 32KB : Wsrc[k][c4]
    __shared__ float  srow[32][68];
    int tid = threadIdx.x;
    for (int i = tid; i < 64 * 32; i += 256) sW[i] = Wsf4[i];
    int c4 = tid & 31;                 // lane id
    int rl = tid >> 5;                 // warp id, 0..7
    float4 bias = __ldg(&((const float4*)bsrc)[c4]);
    float4 av   = __ldg(&((const float4*)attn)[c4]);   // attn[h=c4/8][...]
    int base = blockIdx.x * 32;
    #pragma unroll
    for (int j = 0; j < 4; ++j) {
        int row = base + rl + 8 * j;
        if (row < RG && c4 < 16)
            *(float4*)&srow[rl + 8 * j][c4 * 4] =
                ((const float4*)g_rsum)[(long long)row * 16 + c4];
    }
    __syncthreads();
    unsigned long long a0[4], a1[4];
    #pragma unroll
    for (int j = 0; j < 4; ++j) { a0[j] = 0ull; a1[j] = 0ull; }
    const ulonglong2* sW2 = (const ulonglong2*)sW;
    #pragma unroll 8
    for (int k = 0; k < 64; ++k) {
        ulonglong2 w = sW2[k * 32 + c4];
        #pragma unroll
        for (int j = 0; j < 4; ++j) {
            unsigned long long bb = pack2(srow[rl + 8 * j][k]);
            FMA2(a0[j], w.x, bb);
            FMA2(a1[j], w.y, bb);
        }
    }
    #pragma unroll
    for (int j = 0; j < 4; ++j) {
        int row = base + rl + 8 * j;
        bool valid = (row < RG);
        float4 f;
        f.x = lo32(a0[j]) + bias.x;
        f.y = hi32(a0[j]) + bias.y;
        f.z = lo32(a1[j]) + bias.z;
        f.w = hi32(a1[j]) + bias.w;
        if (valid) ((float4*)g_feat)[(long long)row * 32 + c4] = f;
        // fused prescore (per-head dot of leaky(feat) with attn, then exp)
        float p = leakyf(f.x, 0.2f) * av.x + leakyf(f.y, 0.2f) * av.y +
                  leakyf(f.z, 0.2f) * av.z + leakyf(f.w, 0.2f) * av.w;
        p += __shfl_xor_sync(0xffffffffu, p, 4);
        p += __shfl_xor_sync(0xffffffffu, p, 2);
        p += __shfl_xor_sync(0xffffffffu, p, 1);
        float ex = __expf(p);
        float e1 = __shfl_sync(0xffffffffu, ex, 8);
        float e2 = __shfl_sync(0xffffffffu, ex, 16);
        float e3 = __shfl_sync(0xffffffffu, ex, 24);
        if (c4 == 0 && valid) g_pex[row] = make_float4(ex, e1, e2, e3);
    }
}

// -------- K6: softmax denominators (16B gather + 16B red per edge) --------
__global__ void k_score(const int* __restrict__ src1,
                        const int* __restrict__ dst1) {
    int e = blockIdx.x * blockDim.x + threadIdx.x;
    if (e >= E1C) return;
    int s = __ldg(&src1[e]);
    int d = __ldg(&dst1[e]);
    float4 ex = __ldg((const float4*)&g_pex[s]);
    red_add_v4(&g_ssum[(long long)d * 4], ex);
}

// -------- K7: weighted aggregation into output --------
// 8 lanes per edge; lane sub covers output dims [4*sub, 4*sub+4).
__global__ void k_aggr(const int* __restrict__ src1,
                       const int* __restrict__ dst1,
                       float* __restrict__ out) {
    long long t = (long long)blockIdx.x * blockDim.x + threadIdx.x;
    int e   = (int)(t >> 3);
    int sub = (int)(t & 7);
    if (e >= E1C) return;
    int s = __ldg(&src1[e]);
    int d = __ldg(&dst1[e]);
    float4 exv = __ldg((const float4*)&g_pex[s]);
    float4 sv  = *(const float4*)&g_ssum[(long long)d * 4];
    float a0 = __fdividef(exv.x, sv.x);
    float a1 = __fdividef(exv.y, sv.y);
    float a2 = __fdividef(exv.z, sv.z);
    float a3 = __fdividef(exv.w, sv.w);
    const float4* f4 = (const float4*)g_feat + (long long)s * 32 + sub;
    float4 v0 = __ldg(f4 + 0);
    float4 v1 = __ldg(f4 + 8);
    float4 v2 = __ldg(f4 + 16);
    float4 v3 = __ldg(f4 + 24);
    float4 acc;
    acc.x = a0 * v0.x + a1 * v1.x + a2 * v2.x + a3 * v3.x;
    acc.y = a0 * v0.y + a1 * v1.y + a2 * v2.y + a3 * v3.y;
    acc.z = a0 * v0.z + a1 * v1.z + a2 * v2.z + a3 * v3.z;
    acc.w = a0 * v0.w + a1 * v1.w + a2 * v2.w + a3 * v3.w;
    red_add_v4(&out[(long long)d * 32 + sub * 4], acc);
}

extern "C" void kernel_launch(void* const* d_in, const int* in_sizes, int n_in,
                              void* d_out, int out_size) {
    const float* x          = (const float*)d_in[0];
    const float* norm_n     = (const float*)d_in[1];
    const float* norm_e     = (const float*)d_in[2];
    const float* W1         = (const float*)d_in[3];
    const float* b1         = (const float*)d_in[4];
    const float* Wsrc       = (const float*)d_in[5];
    const float* bsrc       = (const float*)d_in[6];
    const float* attn       = (const float*)d_in[7];
    const int*   src0       = (const int*)d_in[8];
    const int*   dst0       = (const int*)d_in[9];
    const int*   node_graph = (const int*)d_in[10];
    const int*   src1       = (const int*)d_in[11];
    const int*   dst1       = (const int*)d_in[12];
    float* out = (float*)d_out;

    k_init<<<2048, 256>>>(out);
    k_cnt<<<(N0 + 255) / 256, 256>>>(node_graph);
    {
        long long threads = (long long)E0C * 16;
        k_scatter0<<<(unsigned)((threads + 255) / 256), 256>>>(
            (const float4*)x, norm_n, norm_e, src0, dst0, node_graph);
    }
    k_mlp1<<<(RG + 63) / 64, 256>>>((const float4*)W1, b1);
    k_mlp2s<<<(RG + 31) / 32, 256>>>((const float4*)Wsrc, bsrc, attn);
    k_score<<<(E1C + 255) / 256, 256>>>(src1, dst1);
    {
        long long threads = (long long)E1C * 8;
        k_aggr<<<(unsigned)((threads + 255) / 256), 256>>>(src1, dst1, out);
    }
}